// round 8
// baseline (speedup 1.0000x reference)
#include <cuda_runtime.h>
#include <math.h>

#define B 64
#define C 256
#define D 128
#define KTOP 8
#define G2 148
#define TILE 128
#define NCAND (G2*KTOP)
#define QS_LD 68
#define KS_LD 132

// smem float offsets (dynamic smem, sim kernel)
#define OFF_QS   0
#define OFF_KS0  (OFF_QS + D*QS_LD)           // 8704
#define OFF_KS1  (OFF_KS0 + D*KS_LD)          // 25600
#define OFF_SSQ  (OFF_KS1 + D*KS_LD)          // 42496  [2][8][132]
#define OFF_IMP  (OFF_SSQ + 2*8*KS_LD)        // 44608  [2][128]
#define SMEM2_FLOATS (OFF_IMP + 256)          // 44864

// scratch (device globals: no allocations allowed)
__device__ float g_qT[D*B];               // q (unnormalized) transposed [d][b]
__device__ float g_cval[B*G2*KTOP];       // per-block top-8 values
__device__ int   g_cidx[B*G2*KTOP];       // per-block top-8 indices

__device__ __forceinline__ float warpsum(float v) {
    v += __shfl_xor_sync(0xffffffff, v, 16);
    v += __shfl_xor_sync(0xffffffff, v, 8);
    v += __shfl_xor_sync(0xffffffff, v, 4);
    v += __shfl_xor_sync(0xffffffff, v, 2);
    v += __shfl_xor_sync(0xffffffff, v, 1);
    return v;
}

// packed fp32x2 FMA: acc = a*b + acc  (per-lane IEEE fma on both halves)
#define FMA2(acc, a, b) \
    asm("fma.rn.f32x2 %0, %1, %2, %0;" : "+l"(acc) : "l"(a), "l"(b))

#define PACK2(out, f) \
    asm("mov.b64 %0, {%1, %1};" : "=l"(out) : "r"(__float_as_uint(f)))

__device__ __forceinline__ void unpack2(unsigned long long v, float& lo, float& hi) {
    unsigned int a, b;
    asm("mov.b64 {%0, %1}, %2;" : "=r"(a), "=r"(b) : "l"(v));
    lo = __uint_as_float(a); hi = __uint_as_float(b);
}

// ---------------------------------------------------------------------------
// Kernel 1: q = query @ W_q^T + b_q  (no normalization: positive per-row scale
// is top-k order invariant and sim values are selection-only)
// ---------------------------------------------------------------------------
__global__ void qproj_kernel(const float* __restrict__ query,
                             const float* __restrict__ Wq,
                             const float* __restrict__ bq) {
    const int gw   = (blockIdx.x * blockDim.x + threadIdx.x) >> 5;  // 0..2047
    const int lane = threadIdx.x & 31;
    const int b    = gw >> 5;           // 0..63
    const int d0   = (gw & 31) * 4;     // 0,4,...,124

    const float* qr = query + (size_t)b * C;
    const float* w0 = Wq + (size_t)(d0 + 0) * C;
    const float* w1 = Wq + (size_t)(d0 + 1) * C;
    const float* w2 = Wq + (size_t)(d0 + 2) * C;
    const float* w3 = Wq + (size_t)(d0 + 3) * C;

    float a0 = 0.f, a1 = 0.f, a2 = 0.f, a3 = 0.f;
    #pragma unroll
    for (int j = 0; j < 8; j++) {
        int c = lane + 32 * j;
        float q = __ldg(qr + c);
        a0 += q * __ldg(w0 + c);
        a1 += q * __ldg(w1 + c);
        a2 += q * __ldg(w2 + c);
        a3 += q * __ldg(w3 + c);
    }
    #pragma unroll
    for (int off = 16; off; off >>= 1) {
        a0 += __shfl_xor_sync(0xffffffff, a0, off);
        a1 += __shfl_xor_sync(0xffffffff, a1, off);
        a2 += __shfl_xor_sync(0xffffffff, a2, off);
        a3 += __shfl_xor_sync(0xffffffff, a3, off);
    }
    if (lane == 0) {
        g_qT[(d0 + 0) * B + b] = a0 + bq[d0 + 0];
        g_qT[(d0 + 1) * B + b] = a1 + bq[d0 + 1];
        g_qT[(d0 + 2) * B + b] = a2 + bq[d0 + 2];
        g_qT[(d0 + 3) * B + b] = a3 + bq[d0 + 3];
    }
}

// ---------------------------------------------------------------------------
// Kernel 2: 64x128 sim tile via packed f32x2 FMAs, 1 CTA/SM, double-buffered
// key tiles, static interleaved tile schedule, running top-8 (4 scanners/row).
// ---------------------------------------------------------------------------
__global__ void __launch_bounds__(256, 1)
sim_topk_kernel(const float* __restrict__ keys,
                const float* __restrict__ importance,
                int N) {
    extern __shared__ float sm[];
    float* Qs   = sm + OFF_QS;
    float* ssqc = sm + OFF_SSQ;           // [buf][chunk][132], key at col 4m
    float* impb = sm + OFF_IMP;           // [buf][128]

    const int tid = threadIdx.x;          // 256 threads
    const int g   = blockIdx.x;

    // thread roles
    const int m  = tid & 31;              // loader: keys 4m..4m+3
    const int c  = tid >> 5;              // loader: d-chunk 16c..16c+15
    const int ty = tid >> 5, tx = tid & 31;  // GEMM: rows 8ty.., cols 4tx..
    const int rr = tid >> 2, ss = tid & 3;   // scan: 4 scanners per row

    // resident Q (transposed [d][b])
    for (int i = tid; i < D*B; i += 256) {
        int d = i >> 6, bb = i & 63;
        Qs[d*QS_LD + bb] = g_qT[i];
    }

    // running top-8 per (row, 32-col slice) stream
    float tv[KTOP]; int tix[KTOP];
    #pragma unroll
    for (int k = 0; k < KTOP; k++) { tv[k] = -INFINITY; tix[k] = 0; }
    float vmin = -INFINITY; int minpos = 0;

    const int T = (N + TILE - 1) / TILE;

    float4 pf[16];     // 4 keys x 4 float4 (16 d's)
    float  r_imp = 0.f;

    // --- LDG a tile into registers
    auto LDGtile = [&](int t) {
        int base = t * TILE;
        int key0 = base + 4*m;
        #pragma unroll
        for (int kk = 0; kk < 4; kk++) {
            int gk = key0 + kk;
            bool valid = gk < N;
            const float4* kr = reinterpret_cast<const float4*>(keys + (size_t)gk * D);
            #pragma unroll
            for (int dd = 0; dd < 4; dd++)
                pf[kk*4+dd] = valid ? kr[4*c + dd] : make_float4(0.f,0.f,0.f,0.f);
        }
        if (tid < 128) r_imp = (base + tid < N) ? importance[base + tid] : 0.f;
    };

    // --- STS registers -> transposed Ks[buf] + ssq partials + importance
    auto STStile = [&](int buf) {
        float* K = sm + (buf ? OFF_KS1 : OFF_KS0);
        float sq0 = 0.f, sq1 = 0.f, sq2 = 0.f, sq3 = 0.f;
        #pragma unroll
        for (int dd = 0; dd < 4; dd++) {
            float4 a = pf[dd], b = pf[4+dd], cc = pf[8+dd], dv = pf[12+dd];
            int d0 = 16*c + 4*dd;
            *reinterpret_cast<float4*>(K + (d0+0)*KS_LD + 4*m) = make_float4(a.x, b.x, cc.x, dv.x);
            *reinterpret_cast<float4*>(K + (d0+1)*KS_LD + 4*m) = make_float4(a.y, b.y, cc.y, dv.y);
            *reinterpret_cast<float4*>(K + (d0+2)*KS_LD + 4*m) = make_float4(a.z, b.z, cc.z, dv.z);
            *reinterpret_cast<float4*>(K + (d0+3)*KS_LD + 4*m) = make_float4(a.w, b.w, cc.w, dv.w);
            sq0 += a.x*a.x + a.y*a.y + a.z*a.z + a.w*a.w;
            sq1 += b.x*b.x + b.y*b.y + b.z*b.z + b.w*b.w;
            sq2 += cc.x*cc.x + cc.y*cc.y + cc.z*cc.z + cc.w*cc.w;
            sq3 += dv.x*dv.x + dv.y*dv.y + dv.z*dv.z + dv.w*dv.w;
        }
        *reinterpret_cast<float4*>(ssqc + (buf*8 + c)*KS_LD + 4*m) = make_float4(sq0,sq1,sq2,sq3);
        if (tid < 128) impb[buf*128 + tid] = r_imp;
    };

    // --- prologue: load first tile
    if (g < T) { LDGtile(g); STStile(0); }
    __syncthreads();
    int cur = 0;

    for (int tc = g; tc < T; tc += G2, cur ^= 1) {
        float* K = sm + (cur ? OFF_KS1 : OFF_KS0);
        const int tn = tc + G2;
        const bool haven = tn < T;
        if (haven) LDGtile(tn);          // next-tile loads overlap GEMM

        // --- GEMM: 8x4 per thread, f32x2 packed FMAs (row pairs)
        unsigned long long acc[4][4];
        #pragma unroll
        for (int p = 0; p < 4; p++)
            #pragma unroll
            for (int j = 0; j < 4; j++) acc[p][j] = 0ULL;
        {
            const float* qb = Qs + 8*ty;
            const float* kb = K + 4*tx;
            #pragma unroll 4
            for (int d = 0; d < D; d++) {
                float4 k4 = *reinterpret_cast<const float4*>(kb + d*KS_LD);
                ulonglong2 qA = *reinterpret_cast<const ulonglong2*>(qb + d*QS_LD);
                ulonglong2 qB = *reinterpret_cast<const ulonglong2*>(qb + d*QS_LD + 4);
                unsigned long long kk0, kk1, kk2, kk3;
                PACK2(kk0, k4.x); PACK2(kk1, k4.y);
                PACK2(kk2, k4.z); PACK2(kk3, k4.w);
                FMA2(acc[0][0], qA.x, kk0); FMA2(acc[0][1], qA.x, kk1);
                FMA2(acc[0][2], qA.x, kk2); FMA2(acc[0][3], qA.x, kk3);
                FMA2(acc[1][0], qA.y, kk0); FMA2(acc[1][1], qA.y, kk1);
                FMA2(acc[1][2], qA.y, kk2); FMA2(acc[1][3], qA.y, kk3);
                FMA2(acc[2][0], qB.x, kk0); FMA2(acc[2][1], qB.x, kk1);
                FMA2(acc[2][2], qB.x, kk2); FMA2(acc[2][3], qB.x, kk3);
                FMA2(acc[3][0], qB.y, kk0); FMA2(acc[3][1], qB.y, kk1);
                FMA2(acc[3][2], qB.y, kk2); FMA2(acc[3][3], qB.y, kk3);
            }
        }

        // --- scales for this tile's 4 columns (keys 4tx..4tx+3)
        float s0, s1, s2, s3;
        {
            float4 sq = make_float4(0.f,0.f,0.f,0.f);
            const float* sb = ssqc + (cur*8)*KS_LD + 4*tx;
            #pragma unroll
            for (int ch = 0; ch < 8; ch++) {
                float4 v = *reinterpret_cast<const float4*>(sb + ch*KS_LD);
                sq.x += v.x; sq.y += v.y; sq.z += v.z; sq.w += v.w;
            }
            const float* ib = impb + cur*128 + 4*tx;
            s0 = ib[0] / fmaxf(sqrtf(sq.x), 1e-12f);
            s1 = ib[1] / fmaxf(sqrtf(sq.y), 1e-12f);
            s2 = ib[2] / fmaxf(sqrtf(sq.z), 1e-12f);
            s3 = ib[3] / fmaxf(sqrtf(sq.w), 1e-12f);
        }

        __syncthreads();   // A: GEMM reads of K[cur] done; prev scan done

        // --- scaled sims into K[cur] (alias), rows 8ty+2p / +1, cols 4tx..
        #pragma unroll
        for (int p = 0; p < 4; p++) {
            float l0,h0,l1,h1,l2,h2,l3,h3;
            unpack2(acc[p][0], l0, h0); unpack2(acc[p][1], l1, h1);
            unpack2(acc[p][2], l2, h2); unpack2(acc[p][3], l3, h3);
            int r0 = 8*ty + 2*p;
            *reinterpret_cast<float4*>(K + r0*KS_LD + 4*tx)     = make_float4(l0*s0, l1*s1, l2*s2, l3*s3);
            *reinterpret_cast<float4*>(K + (r0+1)*KS_LD + 4*tx) = make_float4(h0*s0, h1*s1, h2*s2, h3*s3);
        }
        if (haven) STStile(cur ^ 1);
        __syncthreads();   // B: sims visible; next key tile staged

        // --- running top-8 update: 4 scanners per row, 32 values each
        {
            int cbase = tc*TILE + 32*ss;
            int avail = N - cbase;
            int cnt = avail < 32 ? (avail < 0 ? 0 : avail) : 32;
            const float* sr = K + rr*KS_LD + 32*ss;
            for (int n = 0; n < cnt; n++) {
                float v = sr[n];
                if (v > vmin) {
                    tv[minpos] = v; tix[minpos] = cbase + n;
                    vmin = tv[0]; minpos = 0;
                    #pragma unroll
                    for (int k = 1; k < KTOP; k++)
                        if (tv[k] < vmin) { vmin = tv[k]; minpos = k; }
                }
            }
        }
    }

    // --- merge 4 scanner streams per row -> 8 candidates per row
    __syncthreads();
    float* bufv = sm + OFF_KS0;                    // alias (loop done)
    int*   bufi = (int*)(sm + OFF_KS0 + 2048);
    #pragma unroll
    for (int k = 0; k < KTOP; k++) { bufv[tid*KTOP + k] = tv[k]; bufi[tid*KTOP + k] = tix[k]; }
    __syncthreads();
    if (tid < 64) {
        float fv[KTOP]; int fi[KTOP];
        #pragma unroll
        for (int k = 0; k < KTOP; k++) { fv[k] = -INFINITY; fi[k] = 0; }
        float fmin = -INFINITY; int fpos = 0;
        int e0 = (4*tid)*KTOP;
        for (int e = 0; e < 4*KTOP; e++) {
            float v = bufv[e0 + e];
            if (v > fmin) {
                fv[fpos] = v; fi[fpos] = bufi[e0 + e];
                fmin = fv[0]; fpos = 0;
                #pragma unroll
                for (int k = 1; k < KTOP; k++)
                    if (fv[k] < fmin) { fmin = fv[k]; fpos = k; }
            }
        }
        int o = (tid*G2 + g)*KTOP;
        #pragma unroll
        for (int k = 0; k < KTOP; k++) { g_cval[o+k] = fv[k]; g_cidx[o+k] = fi[k]; }
    }
}

// ---------------------------------------------------------------------------
// Kernel 3: merge candidates -> global top-8, gather values, softmax attention,
// combine, out = mem @ W_comb^T + b_comb
// ---------------------------------------------------------------------------
__global__ void final_kernel(const float* __restrict__ values,
                             const float* __restrict__ w_attn,
                             const float* __restrict__ b_attn,
                             const float* __restrict__ Wcomb,
                             const float* __restrict__ bcomb,
                             float* __restrict__ out) {
    __shared__ float cv[NCAND];
    __shared__ int   ci[NCAND];
    __shared__ float rv[256];
    __shared__ int   rp[256];
    __shared__ int   topidx[KTOP];
    __shared__ float vs[KTOP*129];
    __shared__ float wa[D];
    __shared__ float ts[KTOP];
    __shared__ float sc[KTOP];
    __shared__ float ms[D];

    const int b = blockIdx.x;
    const int tid = threadIdx.x;          // 256 threads

    for (int i = tid; i < NCAND; i += 256) {
        cv[i] = g_cval[b*NCAND + i];
        ci[i] = g_cidx[b*NCAND + i];
    }
    if (tid < D) wa[tid] = w_attn[tid];
    __syncthreads();

    // 8 rounds of block argmax over candidates
    for (int k = 0; k < KTOP; k++) {
        float best = -INFINITY; int bp = 0;
        for (int i = tid; i < NCAND; i += 256)
            if (cv[i] > best) { best = cv[i]; bp = i; }
        rv[tid] = best; rp[tid] = bp;
        __syncthreads();
        for (int s = 128; s > 0; s >>= 1) {
            if (tid < s && rv[tid+s] > rv[tid]) { rv[tid] = rv[tid+s]; rp[tid] = rp[tid+s]; }
            __syncthreads();
        }
        if (tid == 0) { topidx[k] = ci[rp[0]]; cv[rp[0]] = -INFINITY; }
        __syncthreads();
    }

    // gather retrieved values
    if (tid < D) {
        #pragma unroll
        for (int k = 0; k < KTOP; k++)
            vs[k*129 + tid] = values[(size_t)topidx[k]*D + tid];
    }
    __syncthreads();

    // attention logits
    if (tid < KTOP) {
        float acc = b_attn[0];
        for (int d = 0; d < D; d++) acc += vs[tid*129 + d] * wa[d];
        ts[tid] = acc;
    }
    __syncthreads();
    if (tid == 0) {
        float m = ts[0];
        #pragma unroll
        for (int k = 1; k < KTOP; k++) m = fmaxf(m, ts[k]);
        float e[KTOP]; float s = 0.f;
        #pragma unroll
        for (int k = 0; k < KTOP; k++) { e[k] = expf(ts[k] - m); s += e[k]; }
        #pragma unroll
        for (int k = 0; k < KTOP; k++) sc[k] = e[k] / s;
    }
    __syncthreads();

    // weighted memory
    if (tid < D) {
        float m = 0.f;
        #pragma unroll
        for (int k = 0; k < KTOP; k++) m += sc[k] * vs[k*129 + tid];
        ms[tid] = m;
    }
    __syncthreads();

    // out = mem @ W_comb^T + b_comb  (warp-coalesced matvec)
    const int lane = tid & 31, w = tid >> 5;   // 8 warps
    for (int d = w; d < D; d += 8) {
        const float* wr = Wcomb + (size_t)d*D;
        float acc = 0.f;
        #pragma unroll
        for (int j = 0; j < 4; j++) {
            int e = lane + 32*j;
            acc += ms[e] * wr[e];
        }
        acc = warpsum(acc);
        if (lane == 0) out[b*D + d] = acc + bcomb[d];
    }
}

// ---------------------------------------------------------------------------
extern "C" void kernel_launch(void* const* d_in, const int* in_sizes, int n_in,
                              void* d_out, int out_size) {
    const float* query      = (const float*)d_in[0];
    const float* keys       = (const float*)d_in[1];
    const float* values     = (const float*)d_in[2];
    const float* importance = (const float*)d_in[3];
    const float* Wq         = (const float*)d_in[4];
    const float* bq         = (const float*)d_in[5];
    const float* w_attn     = (const float*)d_in[6];
    const float* b_attn     = (const float*)d_in[7];
    const float* Wcomb      = (const float*)d_in[8];
    const float* bcomb      = (const float*)d_in[9];
    const int N = in_sizes[1] / D;

    const size_t smem2_bytes = (size_t)SMEM2_FLOATS * sizeof(float);
    cudaFuncSetAttribute(sim_topk_kernel,
                         cudaFuncAttributeMaxDynamicSharedMemorySize, (int)smem2_bytes);

    qproj_kernel<<<256, 256>>>(query, Wq, bq);
    sim_topk_kernel<<<G2, 256, smem2_bytes>>>(keys, importance, N);
    final_kernel<<<B, 256>>>(values, w_attn, b_attn, Wcomb, bcomb, (float*)d_out);
}

// round 9
// speedup vs baseline: 1.2104x; 1.2104x over previous
#include <cuda_runtime.h>
#include <math.h>

#define B 64
#define C 256
#define D 128
#define KTOP 8
#define G2 148
#define TILE 128
#define NCAND (G2*KTOP)     // 1184
#define M1 12               // exact-rescore window
#define QS_LD 72            // 72%32=8 -> conflict-free A frags
#define KS_LD 136           // 136%32=8 -> conflict-free B frags

// smem float offsets (dynamic smem, sim kernel)
#define OFF_QS   0                          // 128*72  = 9216
#define OFF_KS0  (OFF_QS + D*QS_LD)         // 9216    (128*136 = 17408)
#define OFF_KS1  (OFF_KS0 + D*KS_LD)        // 26624
#define OFF_SSQ  (OFF_KS1 + D*KS_LD)        // 44032   [2][8][136]
#define OFF_IMP  (OFF_SSQ + 2*8*KS_LD)      // 46208   [2][128]
#define OFF_SCL  (OFF_IMP + 256)            // 46464   [2][128]
#define SMEM2_FLOATS (OFF_SCL + 256)        // 46720 floats = 186880 B

// scratch (device globals: no allocations allowed)
__device__ float g_qT[D*B];               // q (unnormalized) transposed [d][b]
__device__ float g_qRow[B*D];             // q row-major [b][d] (for rescoring)
__device__ float g_cval[B*NCAND];         // per-block top-8 values (tf32 scores)
__device__ int   g_cidx[B*NCAND];         // per-block top-8 indices

__device__ __forceinline__ float warpsum(float v) {
    v += __shfl_xor_sync(0xffffffff, v, 16);
    v += __shfl_xor_sync(0xffffffff, v, 8);
    v += __shfl_xor_sync(0xffffffff, v, 4);
    v += __shfl_xor_sync(0xffffffff, v, 2);
    v += __shfl_xor_sync(0xffffffff, v, 1);
    return v;
}

// m16n8k8 tf32 MMA, fp32 accumulate (raw fp32 bits fed as tf32)
#define MMA_TF32(d0,d1,d2,d3, a0,a1,a2,a3, b0,b1) \
    asm("mma.sync.aligned.m16n8k8.row.col.f32.tf32.tf32.f32 " \
        "{%0,%1,%2,%3}, {%4,%5,%6,%7}, {%8,%9}, {%0,%1,%2,%3};" \
        : "+f"(d0), "+f"(d1), "+f"(d2), "+f"(d3) \
        : "r"(a0), "r"(a1), "r"(a2), "r"(a3), "r"(b0), "r"(b1))

// ---------------------------------------------------------------------------
// Kernel 1: q = query @ W_q^T + b_q  (no normalization: positive per-row scale
// is top-k order invariant and sim values are selection-only)
// ---------------------------------------------------------------------------
__global__ void qproj_kernel(const float* __restrict__ query,
                             const float* __restrict__ Wq,
                             const float* __restrict__ bq) {
    const int gw   = (blockIdx.x * blockDim.x + threadIdx.x) >> 5;  // 0..2047
    const int lane = threadIdx.x & 31;
    const int b    = gw >> 5;           // 0..63
    const int d0   = (gw & 31) * 4;     // 0,4,...,124

    const float* qr = query + (size_t)b * C;
    const float* w0 = Wq + (size_t)(d0 + 0) * C;
    const float* w1 = Wq + (size_t)(d0 + 1) * C;
    const float* w2 = Wq + (size_t)(d0 + 2) * C;
    const float* w3 = Wq + (size_t)(d0 + 3) * C;

    float a0 = 0.f, a1 = 0.f, a2 = 0.f, a3 = 0.f;
    #pragma unroll
    for (int j = 0; j < 8; j++) {
        int c = lane + 32 * j;
        float q = __ldg(qr + c);
        a0 += q * __ldg(w0 + c);
        a1 += q * __ldg(w1 + c);
        a2 += q * __ldg(w2 + c);
        a3 += q * __ldg(w3 + c);
    }
    #pragma unroll
    for (int off = 16; off; off >>= 1) {
        a0 += __shfl_xor_sync(0xffffffff, a0, off);
        a1 += __shfl_xor_sync(0xffffffff, a1, off);
        a2 += __shfl_xor_sync(0xffffffff, a2, off);
        a3 += __shfl_xor_sync(0xffffffff, a3, off);
    }
    if (lane == 0) {
        float v0 = a0 + bq[d0+0], v1 = a1 + bq[d0+1];
        float v2 = a2 + bq[d0+2], v3 = a3 + bq[d0+3];
        g_qT[(d0+0)*B + b] = v0;  g_qT[(d0+1)*B + b] = v1;
        g_qT[(d0+2)*B + b] = v2;  g_qT[(d0+3)*B + b] = v3;
        g_qRow[b*D + d0+0] = v0;  g_qRow[b*D + d0+1] = v1;
        g_qRow[b*D + d0+2] = v2;  g_qRow[b*D + d0+3] = v3;
    }
}

// ---------------------------------------------------------------------------
// Kernel 2: 64x128 sim tile via tf32 tensor-core MMA, 1 CTA/SM, double-
// buffered key tiles, static interleaved schedule, running top-8 per row.
// Warp grid 2(M) x 4(N): warp (wm,wn) computes rows 32wm..+31, keys 32wn..+31
// as 2 M-tiles (m16) x 4 N-strips (n8), K looped 16 x k8.
// ---------------------------------------------------------------------------
__global__ void __launch_bounds__(256, 1)
sim_topk_kernel(const float* __restrict__ keys,
                const float* __restrict__ importance,
                int N) {
    extern __shared__ float sm[];
    float* Qs   = sm + OFF_QS;
    float* ssqc = sm + OFF_SSQ;           // [buf][chunk][KS_LD]
    float* impb = sm + OFF_IMP;           // [buf][128]
    float* scl  = sm + OFF_SCL;           // [buf][128]

    const int tid = threadIdx.x;          // 256 threads
    const int g   = blockIdx.x;

    // roles
    const int m   = tid & 31;             // loader: keys 4m..4m+3
    const int c   = tid >> 5;             // loader: d-chunk 16c..16c+15
    const int wid = tid >> 5, lane = tid & 31;
    const int wm  = wid & 1,  wn  = wid >> 1;      // MMA warp grid
    const int gid = lane >> 2, tig = lane & 3;     // fragment coords
    const int rr  = tid >> 2, ss = tid & 3;        // scan: 4 scanners/row

    // resident Q (transposed [d][b])
    for (int i = tid; i < D*B; i += 256) {
        int d = i >> 6, bb = i & 63;
        Qs[d*QS_LD + bb] = g_qT[i];
    }

    // running top-8 per (row, 32-col slice) stream
    float tv[KTOP]; int tix[KTOP];
    #pragma unroll
    for (int k = 0; k < KTOP; k++) { tv[k] = -INFINITY; tix[k] = 0; }
    float vmin = -INFINITY; int minpos = 0;

    const int T = (N + TILE - 1) / TILE;

    float4 pf[16];     // 4 keys x 4 float4 (16 d's)
    float  r_imp = 0.f;

    auto LDGtile = [&](int t) {
        int base = t * TILE;
        int key0 = base + 4*m;
        #pragma unroll
        for (int kk = 0; kk < 4; kk++) {
            int gk = key0 + kk;
            bool valid = gk < N;
            const float4* kr = reinterpret_cast<const float4*>(keys + (size_t)gk * D);
            #pragma unroll
            for (int dd = 0; dd < 4; dd++)
                pf[kk*4+dd] = valid ? kr[4*c + dd] : make_float4(0.f,0.f,0.f,0.f);
        }
        if (tid < 128) r_imp = (base + tid < N) ? importance[base + tid] : 0.f;
    };

    auto STStile = [&](int buf) {
        float* K = sm + (buf ? OFF_KS1 : OFF_KS0);
        float sq0 = 0.f, sq1 = 0.f, sq2 = 0.f, sq3 = 0.f;
        #pragma unroll
        for (int dd = 0; dd < 4; dd++) {
            float4 a = pf[dd], b = pf[4+dd], cc = pf[8+dd], dv = pf[12+dd];
            int d0 = 16*c + 4*dd;
            *reinterpret_cast<float4*>(K + (d0+0)*KS_LD + 4*m) = make_float4(a.x, b.x, cc.x, dv.x);
            *reinterpret_cast<float4*>(K + (d0+1)*KS_LD + 4*m) = make_float4(a.y, b.y, cc.y, dv.y);
            *reinterpret_cast<float4*>(K + (d0+2)*KS_LD + 4*m) = make_float4(a.z, b.z, cc.z, dv.z);
            *reinterpret_cast<float4*>(K + (d0+3)*KS_LD + 4*m) = make_float4(a.w, b.w, cc.w, dv.w);
            sq0 += a.x*a.x + a.y*a.y + a.z*a.z + a.w*a.w;
            sq1 += b.x*b.x + b.y*b.y + b.z*b.z + b.w*b.w;
            sq2 += cc.x*cc.x + cc.y*cc.y + cc.z*cc.z + cc.w*cc.w;
            sq3 += dv.x*dv.x + dv.y*dv.y + dv.z*dv.z + dv.w*dv.w;
        }
        *reinterpret_cast<float4*>(ssqc + (buf*8 + c)*KS_LD + 4*m) = make_float4(sq0,sq1,sq2,sq3);
        if (tid < 128) impb[buf*128 + tid] = r_imp;
    };

    if (g < T) { LDGtile(g); STStile(0); }
    __syncthreads();
    int cur = 0;

    for (int tc = g; tc < T; tc += G2, cur ^= 1) {
        float* K = sm + (cur ? OFF_KS1 : OFF_KS0);
        const int tn = tc + G2;
        const bool haven = tn < T;

        // --- per-key scale = importance / max(||k||, eps) (exact fp32)
        if (tid < 128) {
            float ssq = 0.f;
            #pragma unroll
            for (int ch = 0; ch < 8; ch++) ssq += ssqc[(cur*8 + ch)*KS_LD + tid];
            scl[cur*128 + tid] = impb[cur*128 + tid] / fmaxf(sqrtf(ssq), 1e-12f);
        }

        if (haven) LDGtile(tn);          // next-tile loads overlap MMA

        // --- tensor-core GEMM: 2 M-tiles x 4 N-strips x 16 k-steps
        float acc[2][4][4];
        #pragma unroll
        for (int mt = 0; mt < 2; mt++)
            #pragma unroll
            for (int sn = 0; sn < 4; sn++)
                #pragma unroll
                for (int r = 0; r < 4; r++) acc[mt][sn][r] = 0.f;

        const int bm = 32*wm, bn = 32*wn;
        #pragma unroll
        for (int k0 = 0; k0 < D; k0 += 8) {
            unsigned int a[2][4], b[4][2];
            #pragma unroll
            for (int mt = 0; mt < 2; mt++) {
                const float* qa = Qs + (k0 + tig)*QS_LD + bm + 16*mt + gid;
                a[mt][0] = __float_as_uint(qa[0]);
                a[mt][1] = __float_as_uint(qa[8]);
                a[mt][2] = __float_as_uint(qa[4*QS_LD]);
                a[mt][3] = __float_as_uint(qa[4*QS_LD + 8]);
            }
            #pragma unroll
            for (int sn = 0; sn < 4; sn++) {
                const float* kb = K + (k0 + tig)*KS_LD + bn + 8*sn + gid;
                b[sn][0] = __float_as_uint(kb[0]);
                b[sn][1] = __float_as_uint(kb[4*KS_LD]);
            }
            #pragma unroll
            for (int mt = 0; mt < 2; mt++)
                #pragma unroll
                for (int sn = 0; sn < 4; sn++)
                    MMA_TF32(acc[mt][sn][0], acc[mt][sn][1], acc[mt][sn][2], acc[mt][sn][3],
                             a[mt][0], a[mt][1], a[mt][2], a[mt][3],
                             b[sn][0], b[sn][1]);
        }

        __syncthreads();   // A: MMA reads of K[cur] done; prev scan done; scl[cur] visible

        // --- scaled sims into K[cur] (alias): rows bm+16mt+gid(+8), cols bn+8sn+2tig(+1)
        #pragma unroll
        for (int mt = 0; mt < 2; mt++) {
            int r0 = bm + 16*mt + gid;
            #pragma unroll
            for (int sn = 0; sn < 4; sn++) {
                int c0 = bn + 8*sn + 2*tig;
                float s0 = scl[cur*128 + c0], s1 = scl[cur*128 + c0 + 1];
                K[r0*KS_LD + c0]       = acc[mt][sn][0] * s0;
                K[r0*KS_LD + c0 + 1]   = acc[mt][sn][1] * s1;
                K[(r0+8)*KS_LD + c0]     = acc[mt][sn][2] * s0;
                K[(r0+8)*KS_LD + c0 + 1] = acc[mt][sn][3] * s1;
            }
        }
        if (haven) STStile(cur ^ 1);
        __syncthreads();   // B: sims visible; next key tile staged

        // --- running top-8 update: 4 scanners per row, 32 values each
        {
            int cbase = tc*TILE + 32*ss;
            int avail = N - cbase;
            int cnt = avail < 32 ? (avail < 0 ? 0 : avail) : 32;
            const float* sr = K + rr*KS_LD + 32*ss;
            for (int n = 0; n < cnt; n++) {
                float v = sr[n];
                if (v > vmin) {
                    tv[minpos] = v; tix[minpos] = cbase + n;
                    vmin = tv[0]; minpos = 0;
                    #pragma unroll
                    for (int k = 1; k < KTOP; k++)
                        if (tv[k] < vmin) { vmin = tv[k]; minpos = k; }
                }
            }
        }
    }

    // --- merge 4 scanner streams per row -> 8 candidates per row
    __syncthreads();
    float* bufv = sm + OFF_KS0;                    // alias (loop done)
    int*   bufi = (int*)(sm + OFF_KS0 + 2048);
    #pragma unroll
    for (int k = 0; k < KTOP; k++) { bufv[tid*KTOP + k] = tv[k]; bufi[tid*KTOP + k] = tix[k]; }
    __syncthreads();
    if (tid < 64) {
        float fv[KTOP]; int fi[KTOP];
        #pragma unroll
        for (int k = 0; k < KTOP; k++) { fv[k] = -INFINITY; fi[k] = 0; }
        float fmin = -INFINITY; int fpos = 0;
        int e0 = (4*tid)*KTOP;
        for (int e = 0; e < 4*KTOP; e++) {
            float v = bufv[e0 + e];
            if (v > fmin) {
                fv[fpos] = v; fi[fpos] = bufi[e0 + e];
                fmin = fv[0]; fpos = 0;
                #pragma unroll
                for (int k = 1; k < KTOP; k++)
                    if (fv[k] < fmin) { fmin = fv[k]; fpos = k; }
            }
        }
        int o = tid*NCAND + g*KTOP;
        #pragma unroll
        for (int k = 0; k < KTOP; k++) { g_cval[o+k] = fv[k]; g_cidx[o+k] = fi[k]; }
    }
}

// ---------------------------------------------------------------------------
// Kernel 3: merge candidates -> tf32 top-M1 -> EXACT fp32 rescore -> top-8,
// gather values, softmax attention, combine, out = mem @ W_comb^T + b_comb
// ---------------------------------------------------------------------------
__global__ void final_kernel(const float* __restrict__ keys,
                             const float* __restrict__ values,
                             const float* __restrict__ importance,
                             const float* __restrict__ w_attn,
                             const float* __restrict__ b_attn,
                             const float* __restrict__ Wcomb,
                             const float* __restrict__ bcomb,
                             float* __restrict__ out,
                             int N) {
    __shared__ float cv[NCAND];
    __shared__ int   ci[NCAND];
    __shared__ float rv[256];
    __shared__ int   rp[256];
    __shared__ int   candIdx[M1];
    __shared__ float rs[M1];
    __shared__ float qrow[D];
    __shared__ int   topidx[KTOP];
    __shared__ float vs[KTOP*129];
    __shared__ float wa[D];
    __shared__ float ts[KTOP];
    __shared__ float sc[KTOP];
    __shared__ float ms[D];

    const int b = blockIdx.x;
    const int tid = threadIdx.x;          // 256 threads
    const int wid = tid >> 5, lane = tid & 31;

    for (int i = tid; i < NCAND; i += 256) {
        cv[i] = g_cval[b*NCAND + i];
        ci[i] = g_cidx[b*NCAND + i];
    }
    if (tid < D) { wa[tid] = w_attn[tid]; qrow[tid] = g_qRow[b*D + tid]; }
    __syncthreads();

    // M1 rounds of block argmax over tf32 candidates
    for (int k = 0; k < M1; k++) {
        float best = -INFINITY; int bp = 0;
        for (int i = tid; i < NCAND; i += 256)
            if (cv[i] > best) { best = cv[i]; bp = i; }
        rv[tid] = best; rp[tid] = bp;
        __syncthreads();
        for (int s = 128; s > 0; s >>= 1) {
            if (tid < s && rv[tid+s] > rv[tid]) { rv[tid] = rv[tid+s]; rp[tid] = rp[tid+s]; }
            __syncthreads();
        }
        if (tid == 0) { candIdx[k] = ci[rp[0]]; cv[rp[0]] = -INFINITY; }
        __syncthreads();
    }

    // EXACT fp32 rescore of the M1 candidates (one warp per candidate)
    for (int j = wid; j < M1; j += 8) {
        int idx = candIdx[j];
        idx = idx < 0 ? 0 : (idx >= N ? N-1 : idx);
        const float4* kr = reinterpret_cast<const float4*>(keys + (size_t)idx * D);
        float4 k4 = kr[lane];
        float4 q4 = *reinterpret_cast<const float4*>(qrow + 4*lane);
        float dot = q4.x*k4.x + q4.y*k4.y + q4.z*k4.z + q4.w*k4.w;
        float ssq = k4.x*k4.x + k4.y*k4.y + k4.z*k4.z + k4.w*k4.w;
        dot = warpsum(dot);
        ssq = warpsum(ssq);
        if (lane == 0)
            rs[j] = importance[idx] * dot / fmaxf(sqrtf(ssq), 1e-12f);
    }
    __syncthreads();

    // exact top-8 of the M1 rescored candidates
    if (tid == 0) {
        #pragma unroll
        for (int k = 0; k < KTOP; k++) {
            float best = -INFINITY; int bp = 0;
            for (int j = 0; j < M1; j++)
                if (rs[j] > best) { best = rs[j]; bp = j; }
            topidx[k] = candIdx[bp];
            rs[bp] = -INFINITY;
        }
    }
    __syncthreads();

    // gather retrieved values
    if (tid < D) {
        #pragma unroll
        for (int k = 0; k < KTOP; k++)
            vs[k*129 + tid] = values[(size_t)topidx[k]*D + tid];
    }
    __syncthreads();

    // attention logits
    if (tid < KTOP) {
        float acc = b_attn[0];
        for (int d = 0; d < D; d++) acc += vs[tid*129 + d] * wa[d];
        ts[tid] = acc;
    }
    __syncthreads();
    if (tid == 0) {
        float mx = ts[0];
        #pragma unroll
        for (int k = 1; k < KTOP; k++) mx = fmaxf(mx, ts[k]);
        float e[KTOP]; float s = 0.f;
        #pragma unroll
        for (int k = 0; k < KTOP; k++) { e[k] = expf(ts[k] - mx); s += e[k]; }
        #pragma unroll
        for (int k = 0; k < KTOP; k++) sc[k] = e[k] / s;
    }
    __syncthreads();

    // weighted memory
    if (tid < D) {
        float mm = 0.f;
        #pragma unroll
        for (int k = 0; k < KTOP; k++) mm += sc[k] * vs[k*129 + tid];
        ms[tid] = mm;
    }
    __syncthreads();

    // out = mem @ W_comb^T + b_comb  (warp-coalesced matvec)
    for (int d = wid; d < D; d += 8) {
        const float* wr = Wcomb + (size_t)d*D;
        float acc = 0.f;
        #pragma unroll
        for (int j = 0; j < 4; j++) {
            int e = lane + 32*j;
            acc += ms[e] * wr[e];
        }
        acc = warpsum(acc);
        if (lane == 0) out[b*D + d] = acc + bcomb[d];
    }
}

// ---------------------------------------------------------------------------
extern "C" void kernel_launch(void* const* d_in, const int* in_sizes, int n_in,
                              void* d_out, int out_size) {
    const float* query      = (const float*)d_in[0];
    const float* keys       = (const float*)d_in[1];
    const float* values     = (const float*)d_in[2];
    const float* importance = (const float*)d_in[3];
    const float* Wq         = (const float*)d_in[4];
    const float* bq         = (const float*)d_in[5];
    const float* w_attn     = (const float*)d_in[6];
    const float* b_attn     = (const float*)d_in[7];
    const float* Wcomb      = (const float*)d_in[8];
    const float* bcomb      = (const float*)d_in[9];
    const int N = in_sizes[1] / D;

    const size_t smem2_bytes = (size_t)SMEM2_FLOATS * sizeof(float);
    cudaFuncSetAttribute(sim_topk_kernel,
                         cudaFuncAttributeMaxDynamicSharedMemorySize, (int)smem2_bytes);

    qproj_kernel<<<256, 256>>>(query, Wq, bq);
    sim_topk_kernel<<<G2, 256, smem2_bytes>>>(keys, importance, N);
    final_kernel<<<B, 256>>>(keys, values, importance, w_attn, b_attn,
                             Wcomb, bcomb, (float*)d_out, N);
}

// round 10
// speedup vs baseline: 1.5371x; 1.2700x over previous
#include <cuda_runtime.h>
#include <cuda_bf16.h>
#include <math.h>

#define B 64
#define C 256
#define D 128
#define KTOP 8
#define G2 148
#define TILE 128
#define NCAND (G2*KTOP)     // 1184
#define M1 16               // exact-rescore window
#define KW 68               // bf16 row stride in 32-bit words (68%32=4 -> conflict-free frags)
#define SIM_LD 132          // sims fp32 row stride

// smem layout in 32-bit words
#define OFF_QW   0                    // Q bf16: 64 rows x 68 words = 4352
#define OFF_K0   4352                 // K bf16 buf0: 128 x 68 = 8704
#define OFF_K1   (4352 + 8704)        // 13056
#define OFF_SCL  (13056 + 8704)       // 21760: scale[128]
#define SMEM_WORDS (21760 + 128)      // 21888 words = 87552 B  -> 2 CTAs/SM

// scratch (device globals: no allocations allowed)
__device__ float g_qRow[B*D];         // q (unnormalized) row-major [b][d]
__device__ float g_cval[B*NCAND];     // per-block top-8 values (bf16-mma scores)
__device__ int   g_cidx[B*NCAND];     // per-block top-8 indices

__device__ __forceinline__ float warpsum(float v) {
    v += __shfl_xor_sync(0xffffffff, v, 16);
    v += __shfl_xor_sync(0xffffffff, v, 8);
    v += __shfl_xor_sync(0xffffffff, v, 4);
    v += __shfl_xor_sync(0xffffffff, v, 2);
    v += __shfl_xor_sync(0xffffffff, v, 1);
    return v;
}

// bf16x2 pack: w = {hi: cvt(h), lo: cvt(l)}
#define CVT2(w, h, l) \
    asm("cvt.rn.bf16x2.f32 %0, %1, %2;" : "=r"(w) : "f"(h), "f"(l))

// m16n8k16 bf16 MMA, fp32 accumulate
#define MMA_BF16(d0,d1,d2,d3, a0,a1,a2,a3, b0,b1) \
    asm("mma.sync.aligned.m16n8k16.row.col.f32.bf16.bf16.f32 " \
        "{%0,%1,%2,%3}, {%4,%5,%6,%7}, {%8,%9}, {%0,%1,%2,%3};" \
        : "+f"(d0), "+f"(d1), "+f"(d2), "+f"(d3) \
        : "r"(a0), "r"(a1), "r"(a2), "r"(a3), "r"(b0), "r"(b1))

// ---------------------------------------------------------------------------
// Kernel 1: q = query @ W_q^T + b_q  (no normalization: positive per-row scale
// is top-k order invariant and sim values are selection-only).
// 4096 warps, 2 outputs each.
// ---------------------------------------------------------------------------
__global__ void qproj_kernel(const float* __restrict__ query,
                             const float* __restrict__ Wq,
                             const float* __restrict__ bq) {
    const int gw   = (blockIdx.x * blockDim.x + threadIdx.x) >> 5;  // 0..4095
    const int lane = threadIdx.x & 31;
    const int b    = gw >> 6;           // 0..63
    const int d0   = (gw & 63) << 1;    // 0,2,...,126

    const float* qr = query + (size_t)b * C;
    const float* w0 = Wq + (size_t)(d0 + 0) * C;
    const float* w1 = Wq + (size_t)(d0 + 1) * C;

    float a0 = 0.f, a1 = 0.f;
    #pragma unroll
    for (int j = 0; j < 8; j++) {
        int c = lane + 32 * j;
        float q = __ldg(qr + c);
        a0 += q * __ldg(w0 + c);
        a1 += q * __ldg(w1 + c);
    }
    #pragma unroll
    for (int off = 16; off; off >>= 1) {
        a0 += __shfl_xor_sync(0xffffffff, a0, off);
        a1 += __shfl_xor_sync(0xffffffff, a1, off);
    }
    if (lane == 0) {
        g_qRow[b*D + d0 + 0] = a0 + bq[d0 + 0];
        g_qRow[b*D + d0 + 1] = a1 + bq[d0 + 1];
    }
}

// ---------------------------------------------------------------------------
// Kernel 2: 64x128 sim tile via bf16 m16n8k16 MMA on NATURAL-layout operands
// (no transpose), double-buffered bf16 key tiles, 2 CTAs/SM, running top-8.
// Warp grid 2(M) x 4(N). Exactness restored later by fp32 rescore of top-M1.
// ---------------------------------------------------------------------------
__global__ void __launch_bounds__(256, 2)
sim_topk_kernel(const float* __restrict__ keys,
                const float* __restrict__ importance,
                int N) {
    extern __shared__ unsigned smw[];          // word-addressed smem
    unsigned* Qw  = smw + OFF_QW;
    float*    scl = (float*)(smw + OFF_SCL);

    const int tid = threadIdx.x;               // 256 threads
    const int g   = blockIdx.x;
    const int wid = tid >> 5, lane = tid & 31;
    const int wm  = wid & 1,  wn  = wid >> 1;  // MMA warp grid 2x4
    const int gid = lane >> 2, tig = lane & 3; // fragment coords
    const int rr  = tid >> 2, ss = tid & 3;    // scan: 4 scanners per row

    // --- resident Q in bf16 natural layout [m][k]: warp w loads rows w+8i
    {
        const float4* qsrc = (const float4*)g_qRow;
        #pragma unroll
        for (int i = 0; i < 8; i++) {
            int r = wid + 8*i;                 // 0..63
            float4 v = qsrc[r*32 + lane];
            unsigned wlo, whi;
            CVT2(wlo, v.y, v.x);
            CVT2(whi, v.w, v.z);
            *reinterpret_cast<uint2*>(Qw + r*KW + lane*2) = make_uint2(wlo, whi);
        }
    }

    // running top-8 per (row, col-slice) stream
    float tv[KTOP]; int tix[KTOP];
    #pragma unroll
    for (int k = 0; k < KTOP; k++) { tv[k] = -INFINITY; tix[k] = 0; }
    float vmin = -INFINITY; int minpos = 0;

    const int T = (N + TILE - 1) / TILE;

    // --- coalesced loader: warp w handles rows w+8i; lane = float4 of row
    auto loadK = [&](int t, unsigned* Kw) {
        int base = t * TILE;
        #pragma unroll 4
        for (int i = 0; i < 16; i++) {
            int r  = wid + 8*i;                // 0..127
            int gk = base + r;
            float4 v = make_float4(0.f,0.f,0.f,0.f);
            if (gk < N)
                v = reinterpret_cast<const float4*>(keys)[(size_t)gk*32 + lane];
            unsigned wlo, whi;
            CVT2(wlo, v.y, v.x);
            CVT2(whi, v.w, v.z);
            *reinterpret_cast<uint2*>(Kw + r*KW + lane*2) = make_uint2(wlo, whi);
        }
    };

    if (g < T) loadK(g, smw + OFF_K0);
    __syncthreads();
    int cur = 0;

    for (int tc = g; tc < T; tc += G2, cur ^= 1) {
        unsigned* Kw = smw + (cur ? OFF_K1 : OFF_K0);
        const int base = tc * TILE;
        const int tn = tc + G2;
        const bool haven = tn < T;

        // --- stage next tile (writes other buffer; overlaps MMA)
        if (haven) loadK(tn, smw + (cur ? OFF_K0 : OFF_K1));

        // --- per-key scale = importance / max(||k||,eps) from bf16 row
        if (tid < 128) {
            int gk = base + tid;
            float ssq = 0.f;
            const uint4* row = reinterpret_cast<const uint4*>(Kw + tid*KW);
            #pragma unroll
            for (int u = 0; u < 16; u++) {     // 64 valid words = 16 uint4
                uint4 w4 = row[u];
                float2 f;
                f = __bfloat1622float2(*reinterpret_cast<const __nv_bfloat162*>(&w4.x)); ssq += f.x*f.x + f.y*f.y;
                f = __bfloat1622float2(*reinterpret_cast<const __nv_bfloat162*>(&w4.y)); ssq += f.x*f.x + f.y*f.y;
                f = __bfloat1622float2(*reinterpret_cast<const __nv_bfloat162*>(&w4.z)); ssq += f.x*f.x + f.y*f.y;
                f = __bfloat1622float2(*reinterpret_cast<const __nv_bfloat162*>(&w4.w)); ssq += f.x*f.x + f.y*f.y;
            }
            float imp = (gk < N) ? importance[gk] : 0.f;
            scl[tid] = imp / fmaxf(sqrtf(ssq), 1e-12f);
        }

        // --- MMA: 2 M-tiles x 4 N-strips x 8 k16-steps, natural layouts
        float acc[2][4][4];
        #pragma unroll
        for (int mt = 0; mt < 2; mt++)
            #pragma unroll
            for (int sn = 0; sn < 4; sn++)
                #pragma unroll
                for (int r = 0; r < 4; r++) acc[mt][sn][r] = 0.f;

        const int bm = 32*wm, bn = 32*wn;
        #pragma unroll
        for (int wk0 = 0; wk0 < 64; wk0 += 8) {      // word k-offset
            unsigned a[2][4], b[4][2];
            #pragma unroll
            for (int mt = 0; mt < 2; mt++) {
                const unsigned* qa = Qw + (bm + 16*mt + gid)*KW + wk0 + tig;
                a[mt][0] = qa[0];
                a[mt][1] = qa[8*KW];
                a[mt][2] = qa[4];
                a[mt][3] = qa[8*KW + 4];
            }
            #pragma unroll
            for (int sn = 0; sn < 4; sn++) {
                const unsigned* kb = Kw + (bn + 8*sn + gid)*KW + wk0 + tig;
                b[sn][0] = kb[0];
                b[sn][1] = kb[4];
            }
            #pragma unroll
            for (int mt = 0; mt < 2; mt++)
                #pragma unroll
                for (int sn = 0; sn < 4; sn++)
                    MMA_BF16(acc[mt][sn][0], acc[mt][sn][1], acc[mt][sn][2], acc[mt][sn][3],
                             a[mt][0], a[mt][1], a[mt][2], a[mt][3],
                             b[sn][0], b[sn][1]);
        }

        __syncthreads();   // 1: K[cur] reads done (mma+ssq); K[nxt] staged; scl visible

        // --- scaled sims into K[cur] region as fp32 [64][SIM_LD]
        float* simsF = (float*)Kw;
        #pragma unroll
        for (int mt = 0; mt < 2; mt++) {
            int r0 = bm + 16*mt + gid;
            #pragma unroll
            for (int sn = 0; sn < 4; sn++) {
                int c0 = bn + 8*sn + 2*tig;
                float s0 = scl[c0], s1 = scl[c0+1];
                simsF[r0*SIM_LD + c0]         = acc[mt][sn][0] * s0;
                simsF[r0*SIM_LD + c0 + 1]     = acc[mt][sn][1] * s1;
                simsF[(r0+8)*SIM_LD + c0]     = acc[mt][sn][2] * s0;
                simsF[(r0+8)*SIM_LD + c0 + 1] = acc[mt][sn][3] * s1;
            }
        }
        __syncthreads();   // 2: sims visible

        // --- running top-8: scanner ss takes cols ss, ss+4, ... (conflict-free)
        {
            float* simsF2 = (float*)Kw;
            int nmax = N - base; if (nmax > TILE) nmax = TILE;
            int cnt = (nmax > ss) ? ((nmax - ss + 3) >> 2) : 0;
            const float* sr = simsF2 + rr*SIM_LD + ss;
            for (int n = 0; n < cnt; n++) {
                float v = sr[4*n];
                if (v > vmin) {
                    tv[minpos] = v; tix[minpos] = base + 4*n + ss;
                    vmin = tv[0]; minpos = 0;
                    #pragma unroll
                    for (int k = 1; k < KTOP; k++)
                        if (tv[k] < vmin) { vmin = tv[k]; minpos = k; }
                }
            }
        }
        __syncthreads();   // 3: scan done -> next iter may overwrite K[cur]
    }

    // --- merge 4 scanner streams per row -> 8 candidates per row
    float* bufv = (float*)(smw + OFF_QW);          // alias Q region (done)
    int*   bufi = (int*)(smw + OFF_QW + 2048);
    #pragma unroll
    for (int k = 0; k < KTOP; k++) { bufv[tid*KTOP + k] = tv[k]; bufi[tid*KTOP + k] = tix[k]; }
    __syncthreads();
    if (tid < 64) {
        float fv[KTOP]; int fi[KTOP];
        #pragma unroll
        for (int k = 0; k < KTOP; k++) { fv[k] = -INFINITY; fi[k] = 0; }
        float fmin = -INFINITY; int fpos = 0;
        int e0 = (4*tid)*KTOP;
        for (int e = 0; e < 4*KTOP; e++) {
            float v = bufv[e0 + e];
            if (v > fmin) {
                fv[fpos] = v; fi[fpos] = bufi[e0 + e];
                fmin = fv[0]; fpos = 0;
                #pragma unroll
                for (int k = 1; k < KTOP; k++)
                    if (fv[k] < fmin) { fmin = fv[k]; fpos = k; }
            }
        }
        int o = tid*NCAND + g*KTOP;
        #pragma unroll
        for (int k = 0; k < KTOP; k++) { g_cval[o+k] = fv[k]; g_cidx[o+k] = fi[k]; }
    }
}

// ---------------------------------------------------------------------------
// Kernel 3: merge candidates -> approx top-M1 -> EXACT fp32 rescore -> top-8,
// gather values, softmax attention, combine, out = mem @ W_comb^T + b_comb
// ---------------------------------------------------------------------------
__global__ void final_kernel(const float* __restrict__ keys,
                             const float* __restrict__ values,
                             const float* __restrict__ importance,
                             const float* __restrict__ w_attn,
                             const float* __restrict__ b_attn,
                             const float* __restrict__ Wcomb,
                             const float* __restrict__ bcomb,
                             float* __restrict__ out,
                             int N) {
    __shared__ float cv[NCAND];
    __shared__ int   ci[NCAND];
    __shared__ float rv[8];
    __shared__ int   rp[8];
    __shared__ int   candIdx[M1];
    __shared__ float rs[M1];
    __shared__ float qrow[D];
    __shared__ int   topidx[KTOP];
    __shared__ float vs[KTOP*129];
    __shared__ float wa[D];
    __shared__ float ts[KTOP];
    __shared__ float sc[KTOP];
    __shared__ float ms[D];

    const int b = blockIdx.x;
    const int tid = threadIdx.x;          // 256 threads
    const int wid = tid >> 5, lane = tid & 31;

    for (int i = tid; i < NCAND; i += 256) {
        cv[i] = g_cval[b*NCAND + i];
        ci[i] = g_cidx[b*NCAND + i];
    }
    if (tid < D) { wa[tid] = w_attn[tid]; qrow[tid] = g_qRow[b*D + tid]; }
    __syncthreads();

    // M1 rounds of argmax (warp-shuffle reduce, 2 syncs/round)
    for (int k = 0; k < M1; k++) {
        float best = -INFINITY; int bp = 0;
        for (int i = tid; i < NCAND; i += 256)
            if (cv[i] > best) { best = cv[i]; bp = i; }
        #pragma unroll
        for (int off = 16; off; off >>= 1) {
            float ov = __shfl_xor_sync(0xffffffff, best, off);
            int   oi = __shfl_xor_sync(0xffffffff, bp, off);
            if (ov > best) { best = ov; bp = oi; }
        }
        if (lane == 0) { rv[wid] = best; rp[wid] = bp; }
        __syncthreads();
        if (tid == 0) {
            float bb = rv[0]; int bi = rp[0];
            #pragma unroll
            for (int w = 1; w < 8; w++)
                if (rv[w] > bb) { bb = rv[w]; bi = rp[w]; }
            candIdx[k] = ci[bi];
            cv[bi] = -INFINITY;
        }
        __syncthreads();
    }

    // EXACT fp32 rescore of the M1 candidates (one warp per candidate)
    for (int j = wid; j < M1; j += 8) {
        int idx = candIdx[j];
        idx = idx < 0 ? 0 : (idx >= N ? N-1 : idx);
        const float4* kr = reinterpret_cast<const float4*>(keys + (size_t)idx * D);
        float4 k4 = kr[lane];
        float4 q4 = *reinterpret_cast<const float4*>(qrow + 4*lane);
        float dot = q4.x*k4.x + q4.y*k4.y + q4.z*k4.z + q4.w*k4.w;
        float ssq = k4.x*k4.x + k4.y*k4.y + k4.z*k4.z + k4.w*k4.w;
        dot = warpsum(dot);
        ssq = warpsum(ssq);
        if (lane == 0)
            rs[j] = importance[idx] * dot / fmaxf(sqrtf(ssq), 1e-12f);
    }
    __syncthreads();

    // exact top-8 of the M1 rescored candidates
    if (tid == 0) {
        #pragma unroll
        for (int k = 0; k < KTOP; k++) {
            float best = -INFINITY; int bp = 0;
            for (int j = 0; j < M1; j++)
                if (rs[j] > best) { best = rs[j]; bp = j; }
            topidx[k] = candIdx[bp];
            rs[bp] = -INFINITY;
        }
    }
    __syncthreads();

    // gather retrieved values
    if (tid < D) {
        #pragma unroll
        for (int k = 0; k < KTOP; k++)
            vs[k*129 + tid] = values[(size_t)topidx[k]*D + tid];
    }
    __syncthreads();

    // attention logits
    if (tid < KTOP) {
        float acc = b_attn[0];
        for (int d = 0; d < D; d++) acc += vs[tid*129 + d] * wa[d];
        ts[tid] = acc;
    }
    __syncthreads();
    if (tid == 0) {
        float mx = ts[0];
        #pragma unroll
        for (int k = 1; k < KTOP; k++) mx = fmaxf(mx, ts[k]);
        float e[KTOP]; float s = 0.f;
        #pragma unroll
        for (int k = 0; k < KTOP; k++) { e[k] = expf(ts[k] - mx); s += e[k]; }
        #pragma unroll
        for (int k = 0; k < KTOP; k++) sc[k] = e[k] / s;
    }
    __syncthreads();

    // weighted memory
    if (tid < D) {
        float mm = 0.f;
        #pragma unroll
        for (int k = 0; k < KTOP; k++) mm += sc[k] * vs[k*129 + tid];
        ms[tid] = mm;
    }
    __syncthreads();

    // out = mem @ W_comb^T + b_comb  (warp-coalesced matvec)
    for (int d = wid; d < D; d += 8) {
        const float* wr = Wcomb + (size_t)d*D;
        float acc = 0.f;
        #pragma unroll
        for (int j = 0; j < 4; j++) {
            int e = lane + 32*j;
            acc += ms[e] * wr[e];
        }
        acc = warpsum(acc);
        if (lane == 0) out[b*D + d] = acc + bcomb[d];
    }
}

// ---------------------------------------------------------------------------
extern "C" void kernel_launch(void* const* d_in, const int* in_sizes, int n_in,
                              void* d_out, int out_size) {
    const float* query      = (const float*)d_in[0];
    const float* keys       = (const float*)d_in[1];
    const float* values     = (const float*)d_in[2];
    const float* importance = (const float*)d_in[3];
    const float* Wq         = (const float*)d_in[4];
    const float* bq         = (const float*)d_in[5];
    const float* w_attn     = (const float*)d_in[6];
    const float* b_attn     = (const float*)d_in[7];
    const float* Wcomb      = (const float*)d_in[8];
    const float* bcomb      = (const float*)d_in[9];
    const int N = in_sizes[1] / D;

    const size_t smem2_bytes = (size_t)SMEM_WORDS * 4;
    cudaFuncSetAttribute(sim_topk_kernel,
                         cudaFuncAttributeMaxDynamicSharedMemorySize, (int)smem2_bytes);

    qproj_kernel<<<512, 256>>>(query, Wq, bq);
    sim_topk_kernel<<<G2, 256, smem2_bytes>>>(keys, importance, N);
    final_kernel<<<B, 256>>>(keys, values, importance, w_attn, b_attn,
                             Wcomb, bcomb, (float*)d_out, N);
}